// round 9
// baseline (speedup 1.0000x reference)
#include <cuda_runtime.h>
#include <cuda_bf16.h>
#include <cstdint>

typedef unsigned long long u64;

// ---------------------------------------------------------------------------
// dilate_block — round 9: mma.sync bf16 split-precision convs,
//   * register-direct A fragments: each lane gathers exactly its own
//     m16n8k16 fragment elements (2 rows x KTILES x 2 float2) -> no A smem,
//     no STS/LDS, no syncs in the mainloop
//   * B fragments via __ldg (L1-resident)
//   * BN stats fused in conv epilogue (ticket last-CTA reduce)
// ---------------------------------------------------------------------------

static constexpr int MAXR = 640000;
static constexpr int MAXBLK = MAXR / 128 + 2;

__device__ __align__(16) float g_A [MAXR * 64];
__device__ __align__(16) float g_B [MAXR * 64];
__device__ __align__(16) float g_C [MAXR * 64];
__device__ __align__(16) float g_X1[MAXR * 64];
__device__ __align__(16) float g_X2[MAXR * 64];
__device__ __align__(16) float g_X3[MAXR * 64];
__device__ float g_pS[MAXBLK * 64];
__device__ float g_pQ[MAXBLK * 64];
__device__ float g_st[4 * 128];
__device__ unsigned g_tick;                             // zero-init, self-resetting
__device__ __align__(16) float g_Wt[3 * 4096];          // down_w packed (fp32 path)
__device__ __align__(16) uint32_t g_Wb[516096];         // conv weights, frag-major hi/lo

// ---------------- helpers ----------------
__device__ __forceinline__ uint32_t cvt2(float lo, float hi) {
    uint32_t r;
    asm("cvt.rn.bf16x2.f32 %0, %1, %2;" : "=r"(r) : "f"(hi), "f"(lo));
    return r;
}
__device__ __forceinline__ void mma_bf16(float d[4], const uint32_t a[4], const uint32_t b[2]) {
    asm volatile(
        "mma.sync.aligned.m16n8k16.row.col.f32.bf16.bf16.f32 "
        "{%0,%1,%2,%3}, {%4,%5,%6,%7}, {%8,%9}, {%0,%1,%2,%3};"
        : "+f"(d[0]), "+f"(d[1]), "+f"(d[2]), "+f"(d[3])
        : "r"(a[0]), "r"(a[1]), "r"(a[2]), "r"(a[3]), "r"(b[0]), "r"(b[1]));
}
__device__ __forceinline__ u64 ffma2(u64 a, u64 b, u64 c) {
    u64 d;
    asm("fma.rn.f32x2 %0, %1, %2, %3;" : "=l"(d) : "l"(a), "l"(b), "l"(c));
    return d;
}

// ---------------------------------------------------------------------------
// weight prep: fp32 [K][CIN][64] -> per tap [term(hi,lo)][kt][nt(8)][lane(32)][reg(2)]
// ---------------------------------------------------------------------------
struct WPtrs { const float* p[13]; };

__global__ void __launch_bounds__(256)
wprep(WPtrs w, uint32_t* __restrict__ dst)
{
    const int nT[13]   = {9,9,9,9,27,9,9,9,9,9,9,9,9};
    const int cinA[13] = {32,64,32,64,64,64,64,64,64,64,64,64,64};
    const int offW[13] = {0,18432,55296,73728,110592,221184,258048,294912,
                          331776,368640,405504,442368,479232};
    int b = blockIdx.x, c = 0;
    while (b >= nT[c]) { b -= nT[c]; ++c; }
    const int CIN = cinA[c];
    const int KT = CIN / 16;
    const float* src = w.p[c] + (size_t)b * CIN * 64;
    uint16_t* hiT = reinterpret_cast<uint16_t*>(dst + offW[c] + (size_t)b * (KT * 1024));
    uint16_t* loT = hiT + KT * 1024;
    for (int e = threadIdx.x; e < CIN * 64; e += 256) {
        const int ci = e >> 6, co = e & 63;
        const float x = src[e];
        __nv_bfloat16 hb = __float2bfloat16(x);
        __nv_bfloat16 lb = __float2bfloat16(x - __bfloat162float(hb));
        const int kt = ci >> 4, ck = (ci & 15) >> 1, j = ci & 1;
        const int regb = (ck >= 4) ? 1 : 0;
        const int tt = ck & 3, nt = co >> 3, gg = co & 7;
        const int word = ((kt * 8 + nt) * 32 + (gg * 4 + tt)) * 2 + regb;
        hiT[word * 2 + j] = *reinterpret_cast<unsigned short*>(&hb);
        loT[word * 2 + j] = *reinterpret_cast<unsigned short*>(&lb);
    }
}

__global__ void wtrans_down(const float* __restrict__ src, float* __restrict__ dst)
{
    const int k = blockIdx.x;
    for (int e = threadIdx.x; e < 4096; e += 256) {
        const int ci = e >> 6, co = e & 63;
        dst[k * 4096 + ((ci >> 2) * 64 + co) * 4 + (ci & 3)] = src[k * 4096 + e];
    }
}

// ---------------------------------------------------------------------------
// mma.sync gather-GEMM conv. 256 thr, 8 warps x 16 rows = 128 rows per block.
// Register-direct A fragments; B via __ldg. Optional fused BN stats.
// ---------------------------------------------------------------------------
template <int KTILES, int KTAPS, bool STATS>
__global__ void __launch_bounds__(256, 2)
mma_conv(const float* __restrict__ in, int nIn,
         const int* __restrict__ nbr, int nOut,
         const uint32_t* __restrict__ Wg,
         float* __restrict__ out,
         float* __restrict__ pSum, float* __restrict__ pSq,
         float* __restrict__ stOut)
{
    constexpr int CIN = KTILES * 16;
    constexpr int TAPW = KTILES * 1024;              // b32 words per tap (hi+lo)
    constexpr int LOW = KTILES * 512;                // lo-block word offset
    constexpr int NR = 2 * KTILES;                   // float2 per row set

    __shared__ float redS[8][64];
    __shared__ float redQ[8][64];
    __shared__ unsigned s_last;

    const int t = threadIdx.x;
    const int w = t >> 5;
    const int l = t & 31;
    const int rowBase = blockIdx.x * 128 + w * 16;

    const int rq = l >> 2;                 // fragment row group 0..7
    const int cp = (l & 3) * 2;            // k-col pair base
    const int row0 = rowBase + rq;
    const int row1 = row0 + 8;
    const bool ok0 = (row0 < nOut);
    const bool ok1 = (row1 < nOut);

    // raw[0..NR-1] = row0 data, raw[NR..2NR-1] = row1 data
    float2 cur[2 * NR], nxt[2 * NR];
    const float2 z2 = make_float2(0.f, 0.f);

    auto load = [&](float2* buf, int k) {
        const int j0 = ok0 ? __ldg(&nbr[(size_t)k * nOut + row0]) : nIn;
        const int j1 = ok1 ? __ldg(&nbr[(size_t)k * nOut + row1]) : nIn;
        const bool v0 = (j0 < nIn);
        const bool v1 = (j1 < nIn);
        const float* p0 = in + (size_t)(v0 ? j0 : 0) * CIN;
        const float* p1 = in + (size_t)(v1 ? j1 : 0) * CIN;
#pragma unroll
        for (int kt = 0; kt < KTILES; ++kt) {
            buf[kt * 2 + 0]      = v0 ? *reinterpret_cast<const float2*>(p0 + kt * 16 + cp)     : z2;
            buf[kt * 2 + 1]      = v0 ? *reinterpret_cast<const float2*>(p0 + kt * 16 + cp + 8) : z2;
            buf[NR + kt * 2 + 0] = v1 ? *reinterpret_cast<const float2*>(p1 + kt * 16 + cp)     : z2;
            buf[NR + kt * 2 + 1] = v1 ? *reinterpret_cast<const float2*>(p1 + kt * 16 + cp + 8) : z2;
        }
    };

    float acc[8][4];
#pragma unroll
    for (int nt = 0; nt < 8; ++nt)
#pragma unroll
        for (int j = 0; j < 4; ++j) acc[nt][j] = 0.f;

    load(cur, 0);

    for (int k = 0; k < KTAPS; ++k) {
        const bool more = (k + 1 < KTAPS);
        if (more) load(nxt, k + 1);
        const uint32_t* wtap = Wg + (size_t)k * TAPW;
#pragma unroll
        for (int kt = 0; kt < KTILES; ++kt) {
            const float2 r00 = cur[kt * 2 + 0];
            const float2 r01 = cur[kt * 2 + 1];
            const float2 r10 = cur[NR + kt * 2 + 0];
            const float2 r11 = cur[NR + kt * 2 + 1];
            uint32_t ah[4], al[4];
            ah[0] = cvt2(r00.x, r00.y);
            ah[1] = cvt2(r10.x, r10.y);
            ah[2] = cvt2(r01.x, r01.y);
            ah[3] = cvt2(r11.x, r11.y);
            al[0] = cvt2(r00.x - __uint_as_float(ah[0] << 16),
                         r00.y - __uint_as_float(ah[0] & 0xFFFF0000u));
            al[1] = cvt2(r10.x - __uint_as_float(ah[1] << 16),
                         r10.y - __uint_as_float(ah[1] & 0xFFFF0000u));
            al[2] = cvt2(r01.x - __uint_as_float(ah[2] << 16),
                         r01.y - __uint_as_float(ah[2] & 0xFFFF0000u));
            al[3] = cvt2(r11.x - __uint_as_float(ah[3] << 16),
                         r11.y - __uint_as_float(ah[3] & 0xFFFF0000u));
#pragma unroll
            for (int nt = 0; nt < 8; ++nt) {
                const uint32_t widx = ((kt * 8 + nt) * 32 + l) * 2;
                const uint2 bhv = __ldg(reinterpret_cast<const uint2*>(wtap + widx));
                const uint2 blv = __ldg(reinterpret_cast<const uint2*>(wtap + LOW + widx));
                uint32_t bh[2] = {bhv.x, bhv.y};
                uint32_t bl[2] = {blv.x, blv.y};
                mma_bf16(acc[nt], ah, bh);
                mma_bf16(acc[nt], al, bh);
                mma_bf16(acc[nt], ah, bl);
            }
        }
        if (more) {
#pragma unroll
            for (int i = 0; i < 2 * NR; ++i) cur[i] = nxt[i];
        }
    }

    // ---- epilogue: write D fragments ----
    const int dg = l >> 2, dt = l & 3;
    const int orow0 = rowBase + dg;
    const int orow1 = orow0 + 8;
    if (orow0 < nOut) {
        float* o = out + (size_t)orow0 * 64 + dt * 2;
#pragma unroll
        for (int nt = 0; nt < 8; ++nt)
            *reinterpret_cast<float2*>(o + nt * 8) = make_float2(acc[nt][0], acc[nt][1]);
    }
    if (orow1 < nOut) {
        float* o = out + (size_t)orow1 * 64 + dt * 2;
#pragma unroll
        for (int nt = 0; nt < 8; ++nt)
            *reinterpret_cast<float2*>(o + nt * 8) = make_float2(acc[nt][2], acc[nt][3]);
    }

    if (STATS) {
#pragma unroll
        for (int nt = 0; nt < 8; ++nt) {
#pragma unroll
            for (int j = 0; j < 2; ++j) {
                float ss = acc[nt][j] + acc[nt][j + 2];
                float qq = acc[nt][j] * acc[nt][j] + acc[nt][j + 2] * acc[nt][j + 2];
                ss += __shfl_xor_sync(0xFFFFFFFFu, ss, 4);
                qq += __shfl_xor_sync(0xFFFFFFFFu, qq, 4);
                ss += __shfl_xor_sync(0xFFFFFFFFu, ss, 8);
                qq += __shfl_xor_sync(0xFFFFFFFFu, qq, 8);
                ss += __shfl_xor_sync(0xFFFFFFFFu, ss, 16);
                qq += __shfl_xor_sync(0xFFFFFFFFu, qq, 16);
                if (l < 4) {
                    redS[w][nt * 8 + l * 2 + j] = ss;
                    redQ[w][nt * 8 + l * 2 + j] = qq;
                }
            }
        }
        __syncthreads();
        if (t < 64) {
            float s = 0.f, q = 0.f;
#pragma unroll
            for (int ww = 0; ww < 8; ++ww) { s += redS[ww][t]; q += redQ[ww][t]; }
            pSum[(size_t)blockIdx.x * 64 + t] = s;
            pSq [(size_t)blockIdx.x * 64 + t] = q;
        }
        __syncthreads();
        __threadfence();
        if (t == 0) s_last = (atomicAdd(&g_tick, 1u) == gridDim.x - 1u) ? 1u : 0u;
        __syncthreads();
        if (s_last) {
            __threadfence();
            const int co = t & 63, sub = t >> 6;
            float s = 0.f, q = 0.f;
            for (int b = sub; b < (int)gridDim.x; b += 4) {
                s += pSum[(size_t)b * 64 + co];
                q += pSq[(size_t)b * 64 + co];
            }
            redS[sub][co] = s;
            redQ[sub][co] = q;
            __syncthreads();
            if (t < 64) {
                const float S = (redS[0][t] + redS[1][t]) + (redS[2][t] + redS[3][t]);
                const float Q = (redQ[0][t] + redQ[1][t]) + (redQ[2][t] + redQ[3][t]);
                const float inv = 1.0f / (float)nOut;
                const float m = S * inv;
                const float var = Q * inv - m * m;
                stOut[t] = m;
                stOut[64 + t] = rsqrtf(var + 1e-5f);
            }
            __syncthreads();
            if (t == 0) g_tick = 0u;
        }
    }
}

// ---------------------------------------------------------------------------
__global__ void bnact_kernel(float4* __restrict__ x, const float* __restrict__ st, long long n4)
{
    const long long i = (long long)blockIdx.x * blockDim.x + threadIdx.x;
    if (i >= n4) return;
    const int c = ((int)(i & 15)) * 4;
    float4 v = x[i];
    v.x = (v.x - st[c + 0]) * st[64 + c + 0];
    v.y = (v.y - st[c + 1]) * st[64 + c + 1];
    v.z = (v.z - st[c + 2]) * st[64 + c + 2];
    v.w = (v.w - st[c + 3]) * st[64 + c + 3];
    v.x = v.x > 0.f ? v.x : 0.01f * v.x;
    v.y = v.y > 0.f ? v.y : 0.01f * v.y;
    v.z = v.z > 0.f ? v.z : 0.01f * v.z;
    v.w = v.w > 0.f ? v.w : 0.01f * v.w;
    x[i] = v;
}

__global__ void combine_kernel(const float4* __restrict__ a, const float* __restrict__ sa,
                               const float4* __restrict__ b, const float* __restrict__ sb,
                               float4* __restrict__ o, long long n4)
{
    const long long i = (long long)blockIdx.x * blockDim.x + threadIdx.x;
    if (i >= n4) return;
    const int c = ((int)(i & 15)) * 4;
    float4 va = a[i];
    float4 vb = b[i];
    float4 r;
    float x;
    x = (va.x - sa[c + 0]) * sa[64 + c + 0]; x = x > 0.f ? x : 0.01f * x; r.x = x;
    x = (va.y - sa[c + 1]) * sa[64 + c + 1]; x = x > 0.f ? x : 0.01f * x; r.y = x;
    x = (va.z - sa[c + 2]) * sa[64 + c + 2]; x = x > 0.f ? x : 0.01f * x; r.z = x;
    x = (va.w - sa[c + 3]) * sa[64 + c + 3]; x = x > 0.f ? x : 0.01f * x; r.w = x;
    x = (vb.x - sb[c + 0]) * sb[64 + c + 0]; x = x > 0.f ? x : 0.01f * x; r.x += x;
    x = (vb.y - sb[c + 1]) * sb[64 + c + 1]; x = x > 0.f ? x : 0.01f * x; r.y += x;
    x = (vb.z - sb[c + 2]) * sb[64 + c + 2]; x = x > 0.f ? x : 0.01f * x; r.z += x;
    x = (vb.w - sb[c + 3]) * sb[64 + c + 3]; x = x > 0.f ? x : 0.01f * x; r.w += x;
    o[i] = r;
}

// out[m] = [x1 | x2 | x3] @ down_w  (fp32 FFMA2 path, warp-autonomous)
__global__ void __launch_bounds__(256)
final_kernel(const float* __restrict__ X1, const float* __restrict__ X2,
             const float* __restrict__ X3, const float* __restrict__ Wp,
             float* __restrict__ out, int M)
{
    __shared__ __align__(16) float buf[8][2][8][64];
    const int t = threadIdx.x;
    const int w = t >> 5;
    const int l = t & 31;
    const int rowBase = (blockIdx.x * 8 + w) * 8;
    const int gr = l >> 2;
    const int gp = l & 3;
    const int grow = rowBase + gr;
    const bool rowOK = (grow < M);

    const float* srcs[3] = {X1, X2, X3};
    auto prefetch = [&](int s, int b) {
        const float* src = srcs[s] + (size_t)(rowOK ? grow : 0) * 64;
        const int sz = rowOK ? 16 : 0;
        const uint32_t dbase = (uint32_t)__cvta_generic_to_shared(&buf[w][b][gr][0]);
#pragma unroll
        for (int i = 0; i < 4; ++i) {
            const int c4 = gp + 4 * i;
            asm volatile("cp.async.ca.shared.global [%0], [%1], 16, %2;\n"
                         :: "r"(dbase + c4 * 16), "l"(src + c4 * 4), "r"(sz));
        }
        asm volatile("cp.async.commit_group;\n");
    };

    u64 accA[8], accB[8];
#pragma unroll
    for (int r = 0; r < 8; ++r) { accA[r] = 0ull; accB[r] = 0ull; }

    prefetch(0, 0);
    for (int s = 0; s < 3; ++s) {
        if (s + 1 < 3) {
            prefetch(s + 1, (s + 1) & 1);
            asm volatile("cp.async.wait_group 1;\n");
        } else {
            asm volatile("cp.async.wait_group 0;\n");
        }
        __syncwarp();
        const float* wk = Wp + (size_t)s * (64 * 64);
        const float* frow = &buf[w][s & 1][0][0];
#pragma unroll
        for (int q = 0; q < 16; ++q) {
            const ulonglong2 wa = *reinterpret_cast<const ulonglong2*>(wk + (q * 64 + l) * 4);
            const ulonglong2 wb = *reinterpret_cast<const ulonglong2*>(wk + (q * 64 + l + 32) * 4);
#pragma unroll
            for (int r = 0; r < 8; ++r) {
                const ulonglong2 s2 =
                    *reinterpret_cast<const ulonglong2*>(frow + r * 64 + q * 4);
                accA[r] = ffma2(s2.x, wa.x, accA[r]);
                accA[r] = ffma2(s2.y, wa.y, accA[r]);
                accB[r] = ffma2(s2.x, wb.x, accB[r]);
                accB[r] = ffma2(s2.y, wb.y, accB[r]);
            }
        }
        __syncwarp();
    }
#pragma unroll
    for (int r = 0; r < 8; ++r) {
        const int orow = rowBase + r;
        if (orow < M) {
            out[(size_t)orow * 64 + l] =
                __uint_as_float((unsigned)accA[r]) + __uint_as_float((unsigned)(accA[r] >> 32));
            out[(size_t)orow * 64 + l + 32] =
                __uint_as_float((unsigned)accB[r]) + __uint_as_float((unsigned)(accB[r] >> 32));
        }
    }
}

// ---------------------------------------------------------------------------
extern "C" void kernel_launch(void* const* d_in, const int* in_sizes, int n_in,
                              void* d_out, int out_size)
{
    const float* feats  = (const float*)d_in[0];
    const float* down_w = (const float*)d_in[14];
    const int* n331_1 = (const int*)d_in[15];
    const int* n313_1 = (const int*)d_in[16];
    const int* pool_n = (const int*)d_in[17];
    const int* n331_2 = (const int*)d_in[18];
    const int* n313_2 = (const int*)d_in[19];
    const int* n331_3 = (const int*)d_in[20];
    const int* n313_3 = (const int*)d_in[21];

    const int N = in_sizes[0] / 32;
    const int M = out_size / 64;

    float *A, *B, *C, *X1, *X2, *X3, *pS, *pQ, *st, *Wt;
    uint32_t* Wb;
    cudaGetSymbolAddress((void**)&A,  g_A);
    cudaGetSymbolAddress((void**)&B,  g_B);
    cudaGetSymbolAddress((void**)&C,  g_C);
    cudaGetSymbolAddress((void**)&X1, g_X1);
    cudaGetSymbolAddress((void**)&X2, g_X2);
    cudaGetSymbolAddress((void**)&X3, g_X3);
    cudaGetSymbolAddress((void**)&pS, g_pS);
    cudaGetSymbolAddress((void**)&pQ, g_pQ);
    cudaGetSymbolAddress((void**)&st, g_st);
    cudaGetSymbolAddress((void**)&Wt, g_Wt);
    cudaGetSymbolAddress((void**)&Wb, g_Wb);
    float* st0 = st;
    float* st1 = st + 128;
    float* st2 = st + 256;
    float* st3 = st + 384;

    const size_t o0 = 0;
    const size_t o1 = 18432;
    const size_t o2 = 55296;
    const size_t o3 = 73728;
    const size_t o4 = 110592;
    const size_t o5 = 221184;
    const size_t o6 = 258048;
    const size_t o7 = 294912;
    const size_t o8 = 331776;
    const size_t o9 = 368640;
    const size_t o10 = 405504;
    const size_t o11 = 442368;
    const size_t o12 = 479232;

    WPtrs wp;
    for (int i = 0; i < 13; ++i) wp.p[i] = (const float*)d_in[1 + i];
    wprep<<<135, 256>>>(wp, Wb);
    wtrans_down<<<3, 256>>>(down_w, Wt);

    const int gN = (N + 127) / 128;
    const int gM = (M + 127) / 128;
    const long long n4N = (long long)N * 16;
    const long long n4M = (long long)M * 16;
    const int gbN = (int)((n4N + 255) / 256);
    const int gbM = (int)((n4M + 255) / 256);
    const int gMf = (M + 63) / 64;

    // ---- block 1 (N rows, 32 -> 64) ----
    mma_conv<2, 9, true><<<gN, 256>>>(feats, N, n331_1, N, Wb + o0, A, pS, pQ, st0);
    bnact_kernel<<<gbN, 256>>>((float4*)A, st0, n4N);
    mma_conv<4, 9, true><<<gN, 256>>>(A, N, n313_1, N, Wb + o1, B, pS, pQ, st1);
    mma_conv<2, 9, true><<<gN, 256>>>(feats, N, n313_1, N, Wb + o2, C, pS, pQ, st2);
    bnact_kernel<<<gbN, 256>>>((float4*)C, st2, n4N);
    mma_conv<4, 9, true><<<gN, 256>>>(C, N, n331_1, N, Wb + o3, A, pS, pQ, st3);
    combine_kernel<<<gbN, 256>>>((const float4*)A, st3, (const float4*)B, st1,
                                 (float4*)C, n4N);

    // ---- pool (K=27): C (N rows) -> X1 (M rows) ----
    mma_conv<4, 27, false><<<gM, 256>>>(C, N, pool_n, M, Wb + o4, X1, nullptr, nullptr, nullptr);

    // ---- block 2 (M rows, dilation 2) ----
    mma_conv<4, 9, true><<<gM, 256>>>(X1, M, n331_2, M, Wb + o5, A, pS, pQ, st0);
    bnact_kernel<<<gbM, 256>>>((float4*)A, st0, n4M);
    mma_conv<4, 9, true><<<gM, 256>>>(A, M, n313_2, M, Wb + o6, B, pS, pQ, st1);
    mma_conv<4, 9, true><<<gM, 256>>>(X1, M, n313_2, M, Wb + o7, C, pS, pQ, st2);
    bnact_kernel<<<gbM, 256>>>((float4*)C, st2, n4M);
    mma_conv<4, 9, true><<<gM, 256>>>(C, M, n331_2, M, Wb + o8, A, pS, pQ, st3);
    combine_kernel<<<gbM, 256>>>((const float4*)A, st3, (const float4*)B, st1,
                                 (float4*)X2, n4M);

    // ---- block 3 (M rows, dilation 3) ----
    mma_conv<4, 9, true><<<gM, 256>>>(X2, M, n331_3, M, Wb + o9, A, pS, pQ, st0);
    bnact_kernel<<<gbM, 256>>>((float4*)A, st0, n4M);
    mma_conv<4, 9, true><<<gM, 256>>>(A, M, n313_3, M, Wb + o10, B, pS, pQ, st1);
    mma_conv<4, 9, true><<<gM, 256>>>(X2, M, n313_3, M, Wb + o11, C, pS, pQ, st2);
    bnact_kernel<<<gbM, 256>>>((float4*)C, st2, n4M);
    mma_conv<4, 9, true><<<gM, 256>>>(C, M, n331_3, M, Wb + o12, A, pS, pQ, st3);
    combine_kernel<<<gbM, 256>>>((const float4*)A, st3, (const float4*)B, st1,
                                 (float4*)X3, n4M);

    // ---- final 1x1 fuse ----
    final_kernel<<<gMf, 256>>>(X1, X2, X3, Wt, (float*)d_out, M);
}

// round 10
// speedup vs baseline: 1.7386x; 1.7386x over previous
#include <cuda_runtime.h>
#include <cuda_bf16.h>
#include <cstdint>

typedef unsigned long long u64;

// ---------------------------------------------------------------------------
// dilate_block — round 10: R7 base (mma.sync bf16 split-precision) plus:
//   * B hi/lo interleaved -> one LDG.128 per (kt,nt) instead of two LDG.64
//   * BN+LeakyReLU fused into consumer conv's gather (bnact kernels deleted)
// ---------------------------------------------------------------------------

static constexpr int MAXR = 640000;
static constexpr int MAXBLK = MAXR / 128 + 2;

__device__ __align__(16) float g_A [MAXR * 64];
__device__ __align__(16) float g_B [MAXR * 64];
__device__ __align__(16) float g_C [MAXR * 64];
__device__ __align__(16) float g_X1[MAXR * 64];
__device__ __align__(16) float g_X2[MAXR * 64];
__device__ __align__(16) float g_X3[MAXR * 64];
__device__ float g_pS[MAXBLK * 64];
__device__ float g_pQ[MAXBLK * 64];
__device__ float g_st[4 * 128];
__device__ unsigned g_tick;                             // zero-init, self-resetting
__device__ __align__(16) float g_Wt[3 * 4096];          // down_w packed (fp32 path)
__device__ __align__(16) uint32_t g_Wb[516096];         // conv weights, frag-major, hi/lo interleaved

// ---------------- helpers ----------------
__device__ __forceinline__ uint32_t smem_u32(const void* p) {
    uint32_t a;
    asm("{ .reg .u64 t; cvta.to.shared.u64 t, %1; cvt.u32.u64 %0, t; }" : "=r"(a) : "l"(p));
    return a;
}
__device__ __forceinline__ uint32_t cvt2(float lo, float hi) {
    uint32_t r;
    asm("cvt.rn.bf16x2.f32 %0, %1, %2;" : "=r"(r) : "f"(hi), "f"(lo));
    return r;
}
__device__ __forceinline__ uint32_t lds32(uint32_t a) {
    uint32_t v;
    asm volatile("ld.shared.b32 %0, [%1];" : "=r"(v) : "r"(a));
    return v;
}
__device__ __forceinline__ void st32(uint32_t a, uint32_t v) {
    asm volatile("st.shared.b32 [%0], %1;" :: "r"(a), "r"(v));
}
__device__ __forceinline__ void mma_bf16(float d[4], const uint32_t a[4], const uint32_t b[2]) {
    asm volatile(
        "mma.sync.aligned.m16n8k16.row.col.f32.bf16.bf16.f32 "
        "{%0,%1,%2,%3}, {%4,%5,%6,%7}, {%8,%9}, {%0,%1,%2,%3};"
        : "+f"(d[0]), "+f"(d[1]), "+f"(d[2]), "+f"(d[3])
        : "r"(a[0]), "r"(a[1]), "r"(a[2]), "r"(a[3]), "r"(b[0]), "r"(b[1]));
}
__device__ __forceinline__ u64 ffma2(u64 a, u64 b, u64 c) {
    u64 d;
    asm("fma.rn.f32x2 %0, %1, %2, %3;" : "=l"(d) : "l"(a), "l"(b), "l"(c));
    return d;
}

// ---------------------------------------------------------------------------
// weight prep: fp32 [K][CIN][64] -> per tap [kt][nt(8)][lane(32)][hi0,hi1,lo0,lo1]
// ---------------------------------------------------------------------------
struct WPtrs { const float* p[13]; };

__global__ void __launch_bounds__(256)
wprep(WPtrs w, uint32_t* __restrict__ dst)
{
    const int nT[13]   = {9,9,9,9,27,9,9,9,9,9,9,9,9};
    const int cinA[13] = {32,64,32,64,64,64,64,64,64,64,64,64,64};
    const int offW[13] = {0,18432,55296,73728,110592,221184,258048,294912,
                          331776,368640,405504,442368,479232};
    int b = blockIdx.x, c = 0;
    while (b >= nT[c]) { b -= nT[c]; ++c; }
    const int CIN = cinA[c];
    const int KT = CIN / 16;
    const float* src = w.p[c] + (size_t)b * CIN * 64;
    uint16_t* tap = reinterpret_cast<uint16_t*>(dst + offW[c] + (size_t)b * (KT * 1024));
    for (int e = threadIdx.x; e < CIN * 64; e += 256) {
        const int ci = e >> 6, co = e & 63;
        const float x = src[e];
        __nv_bfloat16 hb = __float2bfloat16(x);
        __nv_bfloat16 lb = __float2bfloat16(x - __bfloat162float(hb));
        const int kt = ci >> 4, ck = (ci & 15) >> 1, j = ci & 1;
        const int regb = (ck >= 4) ? 1 : 0;
        const int tt = ck & 3, nt = co >> 3, gg = co & 7;
        const int word = (((kt * 8 + nt) * 32 + (gg * 4 + tt)) * 4) + regb;  // hi at +0/+1
        tap[word * 2 + j]       = *reinterpret_cast<unsigned short*>(&hb);
        tap[(word + 2) * 2 + j] = *reinterpret_cast<unsigned short*>(&lb);   // lo at +2/+3
    }
}

__global__ void wtrans_down(const float* __restrict__ src, float* __restrict__ dst)
{
    const int k = blockIdx.x;
    for (int e = threadIdx.x; e < 4096; e += 256) {
        const int ci = e >> 6, co = e & 63;
        dst[k * 4096 + ((ci >> 2) * 64 + co) * 4 + (ci & 3)] = src[k * 4096 + e];
    }
}

// ---------------------------------------------------------------------------
// mma.sync gather-GEMM conv. 256 thr, 8 warps x 16 rows = 128 rows per block.
// Optional fused input BN+LeakyReLU (BN), fused output BN stats (STATS).
// ---------------------------------------------------------------------------
template <int KTILES, int KTAPS, bool STATS, bool BN>
__global__ void __launch_bounds__(256, 2)
mma_conv(const float* __restrict__ in, int nIn,
         const int* __restrict__ nbr, int nOut,
         const uint32_t* __restrict__ Wg,
         float* __restrict__ out,
         float* __restrict__ pSum, float* __restrict__ pSq,
         float* __restrict__ stOut, const float* __restrict__ bnIn)
{
    constexpr int CIN = KTILES * 16;
    constexpr int TAPW = KTILES * 1024;              // b32 words per tap
    constexpr int ATERM_BYTES = KTILES * 4 * 33 * 4; // stride-33 padded frag layout
    constexpr int ABUF_BYTES = 2 * ATERM_BYTES;
    constexpr int NF4 = CIN / 8;

    extern __shared__ __align__(16) char smem[];
    __shared__ float redS[8][64];
    __shared__ float redQ[8][64];
    __shared__ float s_st[128];
    __shared__ unsigned s_last;

    const uint32_t abase = smem_u32(smem);
    const int t = threadIdx.x;
    const int w = t >> 5;
    const int l = t & 31;
    const int rowBase = blockIdx.x * 128 + w * 16;

    const int gr = l >> 1;
    const int part = l & 1;
    const int grow = rowBase + gr;
    const bool rowOK = (grow < nOut);

    if (BN) {
        if (t < 128) s_st[t] = bnIn[t];
        __syncthreads();
    }

    const uint32_t abuf0 = abase + (uint32_t)(w * 2 + 0) * ABUF_BYTES;
    const uint32_t abuf1 = abase + (uint32_t)(w * 2 + 1) * ABUF_BYTES;

    float4 pf[NF4];
    auto prefetch = [&](int k) {
        const int j = rowOK ? __ldg(&nbr[(size_t)k * nOut + grow]) : nIn;
        if (j < nIn) {
            const float4* s = reinterpret_cast<const float4*>(in + (size_t)j * CIN) + part * NF4;
#pragma unroll
            for (int i = 0; i < NF4; ++i) {
                float4 v = s[i];
                if (BN) {
                    const int c4 = (part * NF4 + i) * 4;
                    v.x = (v.x - s_st[c4 + 0]) * s_st[64 + c4 + 0];
                    v.y = (v.y - s_st[c4 + 1]) * s_st[64 + c4 + 1];
                    v.z = (v.z - s_st[c4 + 2]) * s_st[64 + c4 + 2];
                    v.w = (v.w - s_st[c4 + 3]) * s_st[64 + c4 + 3];
                    v.x = v.x > 0.f ? v.x : 0.01f * v.x;
                    v.y = v.y > 0.f ? v.y : 0.01f * v.y;
                    v.z = v.z > 0.f ? v.z : 0.01f * v.z;
                    v.w = v.w > 0.f ? v.w : 0.01f * v.w;
                }
                pf[i] = v;
            }
        } else {
#pragma unroll
            for (int i = 0; i < NF4; ++i) pf[i] = make_float4(0.f, 0.f, 0.f, 0.f);
        }
    };
    auto convert_sts = [&](uint32_t buf) {
#pragma unroll
        for (int i = 0; i < NF4; ++i) {
            const int kt = (KTILES == 4) ? (part * 2 + (i >> 2)) : part;
            const int regb = ((gr >> 3) & 1) | ((i & 2) ? 2 : 0);
            const int lane0 = ((gr & 7) << 2) + ((i & 1) << 1);
            const uint32_t w0 = (uint32_t)(((kt * 4 + regb) * 33 + lane0) * 4);
            const float4 x = pf[i];
            const uint32_t h0 = cvt2(x.x, x.y);
            const uint32_t h1 = cvt2(x.z, x.w);
            const float l0 = x.x - __uint_as_float(h0 << 16);
            const float l1 = x.y - __uint_as_float(h0 & 0xFFFF0000u);
            const float l2 = x.z - __uint_as_float(h1 << 16);
            const float l3 = x.w - __uint_as_float(h1 & 0xFFFF0000u);
            const uint32_t q0 = cvt2(l0, l1);
            const uint32_t q1 = cvt2(l2, l3);
            st32(buf + w0, h0);
            st32(buf + w0 + 4, h1);
            st32(buf + ATERM_BYTES + w0, q0);
            st32(buf + ATERM_BYTES + w0 + 4, q1);
        }
    };

    float acc[8][4];
#pragma unroll
    for (int nt = 0; nt < 8; ++nt)
#pragma unroll
        for (int j = 0; j < 4; ++j) acc[nt][j] = 0.f;

    prefetch(0);
    convert_sts(abuf0);
    __syncwarp();

    for (int k = 0; k < KTAPS; ++k) {
        const uint32_t cur = (k & 1) ? abuf1 : abuf0;
        const uint32_t nxt = (k & 1) ? abuf0 : abuf1;
        if (k + 1 < KTAPS) prefetch(k + 1);
        const uint32_t* wtap = Wg + (size_t)k * TAPW;
#pragma unroll
        for (int kt = 0; kt < KTILES; ++kt) {
            uint32_t ah[4], al[4];
#pragma unroll
            for (int j = 0; j < 4; ++j) {
                const uint32_t ao = (uint32_t)(((kt * 4 + j) * 33 + l) * 4);
                ah[j] = lds32(cur + ao);
                al[j] = lds32(cur + ATERM_BYTES + ao);
            }
#pragma unroll
            for (int nt = 0; nt < 8; ++nt) {
                const uint32_t widx = ((kt * 8 + nt) * 32 + l) * 4;
                const uint4 bv = __ldg(reinterpret_cast<const uint4*>(wtap + widx));
                uint32_t bh[2] = {bv.x, bv.y};
                uint32_t bl[2] = {bv.z, bv.w};
                mma_bf16(acc[nt], ah, bh);
                mma_bf16(acc[nt], al, bh);
                mma_bf16(acc[nt], ah, bl);
            }
        }
        if (k + 1 < KTAPS) convert_sts(nxt);
        __syncwarp();
    }

    // ---- epilogue: write D fragments ----
    const int dg = l >> 2, dt = l & 3;
    const int row0 = rowBase + dg;
    const int row1 = row0 + 8;
    if (row0 < nOut) {
        float* o = out + (size_t)row0 * 64 + dt * 2;
#pragma unroll
        for (int nt = 0; nt < 8; ++nt)
            *reinterpret_cast<float2*>(o + nt * 8) = make_float2(acc[nt][0], acc[nt][1]);
    }
    if (row1 < nOut) {
        float* o = out + (size_t)row1 * 64 + dt * 2;
#pragma unroll
        for (int nt = 0; nt < 8; ++nt)
            *reinterpret_cast<float2*>(o + nt * 8) = make_float2(acc[nt][2], acc[nt][3]);
    }

    if (STATS) {
#pragma unroll
        for (int nt = 0; nt < 8; ++nt) {
#pragma unroll
            for (int j = 0; j < 2; ++j) {
                float ss = acc[nt][j] + acc[nt][j + 2];
                float qq = acc[nt][j] * acc[nt][j] + acc[nt][j + 2] * acc[nt][j + 2];
                ss += __shfl_xor_sync(0xFFFFFFFFu, ss, 4);
                qq += __shfl_xor_sync(0xFFFFFFFFu, qq, 4);
                ss += __shfl_xor_sync(0xFFFFFFFFu, ss, 8);
                qq += __shfl_xor_sync(0xFFFFFFFFu, qq, 8);
                ss += __shfl_xor_sync(0xFFFFFFFFu, ss, 16);
                qq += __shfl_xor_sync(0xFFFFFFFFu, qq, 16);
                if (l < 4) {
                    redS[w][nt * 8 + l * 2 + j] = ss;
                    redQ[w][nt * 8 + l * 2 + j] = qq;
                }
            }
        }
        __syncthreads();
        if (t < 64) {
            float s = 0.f, q = 0.f;
#pragma unroll
            for (int ww = 0; ww < 8; ++ww) { s += redS[ww][t]; q += redQ[ww][t]; }
            pSum[(size_t)blockIdx.x * 64 + t] = s;
            pSq [(size_t)blockIdx.x * 64 + t] = q;
        }
        __syncthreads();
        __threadfence();
        if (t == 0) s_last = (atomicAdd(&g_tick, 1u) == gridDim.x - 1u) ? 1u : 0u;
        __syncthreads();
        if (s_last) {
            __threadfence();
            const int co = t & 63, sub = t >> 6;
            float s = 0.f, q = 0.f;
            for (int b = sub; b < (int)gridDim.x; b += 4) {
                s += pSum[(size_t)b * 64 + co];
                q += pSq[(size_t)b * 64 + co];
            }
            redS[sub][co] = s;
            redQ[sub][co] = q;
            __syncthreads();
            if (t < 64) {
                const float S = (redS[0][t] + redS[1][t]) + (redS[2][t] + redS[3][t]);
                const float Q = (redQ[0][t] + redQ[1][t]) + (redQ[2][t] + redQ[3][t]);
                const float inv = 1.0f / (float)nOut;
                const float m = S * inv;
                const float var = Q * inv - m * m;
                stOut[t] = m;
                stOut[64 + t] = rsqrtf(var + 1e-5f);
            }
            __syncthreads();
            if (t == 0) g_tick = 0u;
        }
    }
}

// ---------------------------------------------------------------------------
__global__ void combine_kernel(const float4* __restrict__ a, const float* __restrict__ sa,
                               const float4* __restrict__ b, const float* __restrict__ sb,
                               float4* __restrict__ o, long long n4)
{
    const long long i = (long long)blockIdx.x * blockDim.x + threadIdx.x;
    if (i >= n4) return;
    const int c = ((int)(i & 15)) * 4;
    float4 va = a[i];
    float4 vb = b[i];
    float4 r;
    float x;
    x = (va.x - sa[c + 0]) * sa[64 + c + 0]; x = x > 0.f ? x : 0.01f * x; r.x = x;
    x = (va.y - sa[c + 1]) * sa[64 + c + 1]; x = x > 0.f ? x : 0.01f * x; r.y = x;
    x = (va.z - sa[c + 2]) * sa[64 + c + 2]; x = x > 0.f ? x : 0.01f * x; r.z = x;
    x = (va.w - sa[c + 3]) * sa[64 + c + 3]; x = x > 0.f ? x : 0.01f * x; r.w = x;
    x = (vb.x - sb[c + 0]) * sb[64 + c + 0]; x = x > 0.f ? x : 0.01f * x; r.x += x;
    x = (vb.y - sb[c + 1]) * sb[64 + c + 1]; x = x > 0.f ? x : 0.01f * x; r.y += x;
    x = (vb.z - sb[c + 2]) * sb[64 + c + 2]; x = x > 0.f ? x : 0.01f * x; r.z += x;
    x = (vb.w - sb[c + 3]) * sb[64 + c + 3]; x = x > 0.f ? x : 0.01f * x; r.w += x;
    o[i] = r;
}

// out[m] = [x1 | x2 | x3] @ down_w  (fp32 FFMA2 path, warp-autonomous)
__global__ void __launch_bounds__(256)
final_kernel(const float* __restrict__ X1, const float* __restrict__ X2,
             const float* __restrict__ X3, const float* __restrict__ Wp,
             float* __restrict__ out, int M)
{
    __shared__ __align__(16) float buf[8][2][8][64];
    const int t = threadIdx.x;
    const int w = t >> 5;
    const int l = t & 31;
    const int rowBase = (blockIdx.x * 8 + w) * 8;
    const int gr = l >> 2;
    const int gp = l & 3;
    const int grow = rowBase + gr;
    const bool rowOK = (grow < M);

    const float* srcs[3] = {X1, X2, X3};
    auto prefetch = [&](int s, int b) {
        const float* src = srcs[s] + (size_t)(rowOK ? grow : 0) * 64;
        const int sz = rowOK ? 16 : 0;
        const uint32_t dbase = (uint32_t)__cvta_generic_to_shared(&buf[w][b][gr][0]);
#pragma unroll
        for (int i = 0; i < 4; ++i) {
            const int c4 = gp + 4 * i;
            asm volatile("cp.async.ca.shared.global [%0], [%1], 16, %2;\n"
                         :: "r"(dbase + c4 * 16), "l"(src + c4 * 4), "r"(sz));
        }
        asm volatile("cp.async.commit_group;\n");
    };

    u64 accA[8], accB[8];
#pragma unroll
    for (int r = 0; r < 8; ++r) { accA[r] = 0ull; accB[r] = 0ull; }

    prefetch(0, 0);
    for (int s = 0; s < 3; ++s) {
        if (s + 1 < 3) {
            prefetch(s + 1, (s + 1) & 1);
            asm volatile("cp.async.wait_group 1;\n");
        } else {
            asm volatile("cp.async.wait_group 0;\n");
        }
        __syncwarp();
        const float* wk = Wp + (size_t)s * (64 * 64);
        const float* frow = &buf[w][s & 1][0][0];
#pragma unroll
        for (int q = 0; q < 16; ++q) {
            const ulonglong2 wa = *reinterpret_cast<const ulonglong2*>(wk + (q * 64 + l) * 4);
            const ulonglong2 wb = *reinterpret_cast<const ulonglong2*>(wk + (q * 64 + l + 32) * 4);
#pragma unroll
            for (int r = 0; r < 8; ++r) {
                const ulonglong2 s2 =
                    *reinterpret_cast<const ulonglong2*>(frow + r * 64 + q * 4);
                accA[r] = ffma2(s2.x, wa.x, accA[r]);
                accA[r] = ffma2(s2.y, wa.y, accA[r]);
                accB[r] = ffma2(s2.x, wb.x, accB[r]);
                accB[r] = ffma2(s2.y, wb.y, accB[r]);
            }
        }
        __syncwarp();
    }
#pragma unroll
    for (int r = 0; r < 8; ++r) {
        const int orow = rowBase + r;
        if (orow < M) {
            out[(size_t)orow * 64 + l] =
                __uint_as_float((unsigned)accA[r]) + __uint_as_float((unsigned)(accA[r] >> 32));
            out[(size_t)orow * 64 + l + 32] =
                __uint_as_float((unsigned)accB[r]) + __uint_as_float((unsigned)(accB[r] >> 32));
        }
    }
}

// ---------------------------------------------------------------------------
extern "C" void kernel_launch(void* const* d_in, const int* in_sizes, int n_in,
                              void* d_out, int out_size)
{
    const float* feats  = (const float*)d_in[0];
    const float* down_w = (const float*)d_in[14];
    const int* n331_1 = (const int*)d_in[15];
    const int* n313_1 = (const int*)d_in[16];
    const int* pool_n = (const int*)d_in[17];
    const int* n331_2 = (const int*)d_in[18];
    const int* n313_2 = (const int*)d_in[19];
    const int* n331_3 = (const int*)d_in[20];
    const int* n313_3 = (const int*)d_in[21];

    const int N = in_sizes[0] / 32;
    const int M = out_size / 64;

    float *A, *B, *C, *X1, *X2, *X3, *pS, *pQ, *st, *Wt;
    uint32_t* Wb;
    cudaGetSymbolAddress((void**)&A,  g_A);
    cudaGetSymbolAddress((void**)&B,  g_B);
    cudaGetSymbolAddress((void**)&C,  g_C);
    cudaGetSymbolAddress((void**)&X1, g_X1);
    cudaGetSymbolAddress((void**)&X2, g_X2);
    cudaGetSymbolAddress((void**)&X3, g_X3);
    cudaGetSymbolAddress((void**)&pS, g_pS);
    cudaGetSymbolAddress((void**)&pQ, g_pQ);
    cudaGetSymbolAddress((void**)&st, g_st);
    cudaGetSymbolAddress((void**)&Wt, g_Wt);
    cudaGetSymbolAddress((void**)&Wb, g_Wb);
    float* st0 = st;
    float* st1 = st + 128;
    float* st2 = st + 256;
    float* st3 = st + 384;

    const size_t o0 = 0;
    const size_t o1 = 18432;
    const size_t o2 = 55296;
    const size_t o3 = 73728;
    const size_t o4 = 110592;
    const size_t o5 = 221184;
    const size_t o6 = 258048;
    const size_t o7 = 294912;
    const size_t o8 = 331776;
    const size_t o9 = 368640;
    const size_t o10 = 405504;
    const size_t o11 = 442368;
    const size_t o12 = 479232;

    // dynamic smem: A frag buffers (8 warps x 2 bufs x (hi+lo))
    const int SM2 = 8 * 2 * (2 * 2 * 4 * 33 * 4);   // KTILES=2: 33792
    const int SM4 = 8 * 2 * (2 * 4 * 4 * 33 * 4);   // KTILES=4: 67584
    cudaFuncSetAttribute(mma_conv<2, 9, true, false>,
                         cudaFuncAttributeMaxDynamicSharedMemorySize, SM2);
    cudaFuncSetAttribute(mma_conv<4, 9, true, false>,
                         cudaFuncAttributeMaxDynamicSharedMemorySize, SM4);
    cudaFuncSetAttribute(mma_conv<4, 9, true, true>,
                         cudaFuncAttributeMaxDynamicSharedMemorySize, SM4);
    cudaFuncSetAttribute(mma_conv<4, 27, false, false>,
                         cudaFuncAttributeMaxDynamicSharedMemorySize, SM4);

    WPtrs wp;
    for (int i = 0; i < 13; ++i) wp.p[i] = (const float*)d_in[1 + i];
    wprep<<<135, 256>>>(wp, Wb);
    wtrans_down<<<3, 256>>>(down_w, Wt);

    const int gN = (N + 127) / 128;
    const int gM = (M + 127) / 128;
    const long long n4N = (long long)N * 16;
    const long long n4M = (long long)M * 16;
    const int gbN = (int)((n4N + 255) / 256);
    const int gbM = (int)((n4M + 255) / 256);
    const int gMf = (M + 63) / 64;

    // ---- block 1 (N rows, 32 -> 64) ----
    mma_conv<2, 9, true, false><<<gN, 256, SM2>>>(feats, N, n331_1, N, Wb + o0, A, pS, pQ, st0, nullptr);
    mma_conv<4, 9, true, true ><<<gN, 256, SM4>>>(A,     N, n313_1, N, Wb + o1, B, pS, pQ, st1, st0);
    mma_conv<2, 9, true, false><<<gN, 256, SM2>>>(feats, N, n313_1, N, Wb + o2, C, pS, pQ, st2, nullptr);
    mma_conv<4, 9, true, true ><<<gN, 256, SM4>>>(C,     N, n331_1, N, Wb + o3, A, pS, pQ, st3, st2);
    combine_kernel<<<gbN, 256>>>((const float4*)A, st3, (const float4*)B, st1,
                                 (float4*)C, n4N);

    // ---- pool (K=27): C (N rows) -> X1 (M rows) ----
    mma_conv<4, 27, false, false><<<gM, 256, SM4>>>(C, N, pool_n, M, Wb + o4, X1,
                                                    nullptr, nullptr, nullptr, nullptr);

    // ---- block 2 (M rows, dilation 2) ----
    mma_conv<4, 9, true, false><<<gM, 256, SM4>>>(X1, M, n331_2, M, Wb + o5, A, pS, pQ, st0, nullptr);
    mma_conv<4, 9, true, true ><<<gM, 256, SM4>>>(A,  M, n313_2, M, Wb + o6, B, pS, pQ, st1, st0);
    mma_conv<4, 9, true, false><<<gM, 256, SM4>>>(X1, M, n313_2, M, Wb + o7, C, pS, pQ, st2, nullptr);
    mma_conv<4, 9, true, true ><<<gM, 256, SM4>>>(C,  M, n331_2, M, Wb + o8, A, pS, pQ, st3, st2);
    combine_kernel<<<gbM, 256>>>((const float4*)A, st3, (const float4*)B, st1,
                                 (float4*)X2, n4M);

    // ---- block 3 (M rows, dilation 3) ----
    mma_conv<4, 9, true, false><<<gM, 256, SM4>>>(X2, M, n331_3, M, Wb + o9,  A, pS, pQ, st0, nullptr);
    mma_conv<4, 9, true, true ><<<gM, 256, SM4>>>(A,  M, n313_3, M, Wb + o10, B, pS, pQ, st1, st0);
    mma_conv<4, 9, true, false><<<gM, 256, SM4>>>(X2, M, n313_3, M, Wb + o11, C, pS, pQ, st2, nullptr);
    mma_conv<4, 9, true, true ><<<gM, 256, SM4>>>(C,  M, n331_3, M, Wb + o12, A, pS, pQ, st3, st2);
    combine_kernel<<<gbM, 256>>>((const float4*)A, st3, (const float4*)B, st1,
                                 (float4*)X3, n4M);

    // ---- final 1x1 fuse ----
    final_kernel<<<gMf, 256>>>(X1, X2, X3, Wt, (float*)d_out, M);
}